// round 14
// baseline (speedup 1.0000x reference)
#include <cuda_runtime.h>
#include <cuda_fp16.h>
#include <cstdint>

#define BATCH 2
#define SEQ 2048
#define DIM 1024
#define NHEADS 16
#define HDIM 64
#define QSCALE 0.1803368801111204f   // (1/8) * log2(e)
#define MROWS 4096

// ---------------------------------------------------------------------------
// Scratch (device globals: allocation-free)
// ---------------------------------------------------------------------------
__device__ __align__(16) __half g_xh [(size_t)MROWS * DIM];
__device__ __align__(16) __half g_wqh[(size_t)3 * DIM * DIM];
__device__ __align__(16) __half g_wph[(size_t)DIM * DIM];
__device__ __align__(16) __half g_aoh[(size_t)MROWS * DIM];

#define QKV_ELEMS ((size_t)BATCH * NHEADS * SEQ * HDIM)
__device__ __align__(16) __half g_q[QKV_ELEMS];   // pre-scaled by QSCALE
__device__ __align__(16) __half g_k[QKV_ELEMS];
__device__ __align__(16) __half g_v[QKV_ELEMS];

// ---------------------------------------------------------------------------
// Base-ISA helpers
// ---------------------------------------------------------------------------
__device__ __forceinline__ uint32_t smem_u32(const void* p) {
    uint32_t a;
    asm("{ .reg .u64 t; cvta.to.shared.u64 t, %1; cvt.u32.u64 %0, t; }"
        : "=r"(a) : "l"(p));
    return a;
}
__device__ __forceinline__ void ldsm4(uint32_t* r, uint32_t a) {
    asm volatile("ldmatrix.sync.aligned.m8n8.x4.shared.b16 {%0,%1,%2,%3}, [%4];"
        : "=r"(r[0]), "=r"(r[1]), "=r"(r[2]), "=r"(r[3]) : "r"(a));
}
__device__ __forceinline__ void ldsm4t(uint32_t* r, uint32_t a) {
    asm volatile("ldmatrix.sync.aligned.m8n8.x4.trans.shared.b16 {%0,%1,%2,%3}, [%4];"
        : "=r"(r[0]), "=r"(r[1]), "=r"(r[2]), "=r"(r[3]) : "r"(a));
}
__device__ __forceinline__ void mma_f16(float* c, const uint32_t* a, const uint32_t* b) {
    asm volatile(
        "mma.sync.aligned.m16n8k16.row.col.f32.f16.f16.f32 "
        "{%0,%1,%2,%3}, {%4,%5,%6,%7}, {%8,%9}, {%0,%1,%2,%3};"
        : "+f"(c[0]), "+f"(c[1]), "+f"(c[2]), "+f"(c[3])
        : "r"(a[0]), "r"(a[1]), "r"(a[2]), "r"(a[3]), "r"(b[0]), "r"(b[1]));
}
#define CPA16(d, s) \
    asm volatile("cp.async.cg.shared.global [%0], [%1], 16;" :: "r"(d), "l"(s))
#define CP_COMMIT() asm volatile("cp.async.commit_group;" ::: "memory")

__device__ __forceinline__ float ex2(float x) {
    float r; asm("ex2.approx.f32 %0, %1;" : "=f"(r) : "f"(x)); return r;
}
__device__ __forceinline__ uint32_t pack2h(float x, float y) {
    __half2 t = __floats2half2_rn(x, y);
    return *reinterpret_cast<uint32_t*>(&t);
}

// ---------------------------------------------------------------------------
// Merged split: one launch, 16 floats per thread.
// ---------------------------------------------------------------------------
#define XN  ((size_t)MROWS * DIM)        // 4M
#define WQN ((size_t)3 * DIM * DIM)      // 3M

__global__ void split_all(const float* __restrict__ x,
                          const float* __restrict__ wq,
                          const float* __restrict__ wp)
{
    size_t idx = (size_t)blockIdx.x * 4096 + (size_t)threadIdx.x * 16;
    const float* src;
    __half* dst;
    if (idx < XN)            { src = x  + idx;              dst = g_xh  + idx; }
    else if (idx < XN + WQN) { src = wq + (idx - XN);       dst = g_wqh + (idx - XN); }
    else                     { src = wp + (idx - XN - WQN); dst = g_wph + (idx - XN - WQN); }
#pragma unroll
    for (int i = 0; i < 2; i++) {
        float4 a = *(const float4*)(src + i * 8);
        float4 b = *(const float4*)(src + i * 8 + 4);
        *(uint2*)(dst + i * 8)     = make_uint2(pack2h(a.x, a.y), pack2h(a.z, a.w));
        *(uint2*)(dst + i * 8 + 4) = make_uint2(pack2h(b.x, b.y), pack2h(b.z, b.w));
    }
}

// ---------------------------------------------------------------------------
// QKV GEMM (proven R12/R13): CTA 128x64, 3 CTAs/SM, fused fp16 Q/K/V epilogue.
// ---------------------------------------------------------------------------
#define GST 24576
#define GBOFF 16384
#define GSMEM (3 * GST)
#define NCHT 16

__global__ __launch_bounds__(256, 3)
void gemm_qkv()
{
    extern __shared__ char sm[];
    const uint32_t sb = smem_u32(sm);
    const int tid = threadIdx.x, lane = tid & 31, wid = tid >> 5;
    const int wm = wid >> 1, wn = wid & 1;
    const int bm = blockIdx.y * 128, bn = blockIdx.x * 64;

    const int lra = tid >> 1;
    const int lca = (tid & 1) * 4;
    const int lrb = tid >> 2;
    const int lcb = (tid & 3) * 2;

    auto load_stage = [&](int ch, int s) {
        const int co = ch * 64;
        uint32_t abase = sb + s * GST + lra * 128;
        const __half* a = g_xh + (size_t)(bm + lra) * DIM + co;
#pragma unroll
        for (int i = 0; i < 4; i++) {
            int c16 = lca + i;
            CPA16(abase + (uint32_t)((c16 ^ (lra & 7)) << 4), a + c16 * 8);
        }
        uint32_t bbase = sb + s * GST + GBOFF + lrb * 128;
        const __half* b = g_wqh + (size_t)(bn + lrb) * DIM + co;
#pragma unroll
        for (int i = 0; i < 2; i++) {
            int c16 = lcb + i;
            CPA16(bbase + (uint32_t)((c16 ^ (lrb & 7)) << 4), b + c16 * 8);
        }
        CP_COMMIT();
    };

    load_stage(0, 0);
    load_stage(1, 1);

    float acc[2][4][4];
#pragma unroll
    for (int i = 0; i < 2; i++)
#pragma unroll
        for (int j = 0; j < 4; j++)
#pragma unroll
            for (int q = 0; q < 4; q++) acc[i][j][q] = 0.f;

    const int arow0 = wm * 32 + (lane & 15);
    const int alc = lane >> 4;
    const int brow0 = wn * 32 + ((lane >> 4) & 1) * 8 + (lane & 7);
    const int bc = (lane >> 3) & 1;

    for (int ch = 0; ch < NCHT; ch++) {
        const int s = ch % 3;
        if (ch + 1 < NCHT) { asm volatile("cp.async.wait_group 1;" ::: "memory"); }
        else               { asm volatile("cp.async.wait_group 0;" ::: "memory"); }
        __syncthreads();
        const uint32_t Ab = sb + s * GST;
        const uint32_t Bb = Ab + GBOFF;
#pragma unroll
        for (int kk = 0; kk < 4; kk++) {
            uint32_t a0[4], a1[4];
            {
                int c = kk * 2 + alc;
                int r0 = arow0;
                ldsm4(a0, Ab + r0 * 128 + ((c ^ (r0 & 7)) << 4));
                int r1 = arow0 + 16;
                ldsm4(a1, Ab + r1 * 128 + ((c ^ (r1 & 7)) << 4));
            }
#pragma unroll
            for (int bp = 0; bp < 2; bp++) {
                uint32_t b[4];
                int r = brow0 + bp * 16;
                int c = kk * 2 + bc;
                ldsm4(b, Bb + r * 128 + ((c ^ (r & 7)) << 4));
                mma_f16(acc[0][2 * bp],     a0, b);
                mma_f16(acc[0][2 * bp + 1], a0, b + 2);
                mma_f16(acc[1][2 * bp],     a1, b);
                mma_f16(acc[1][2 * bp + 1], a1, b + 2);
            }
        }
        if (ch + 2 < NCHT) load_stage(ch + 2, (ch + 2) % 3);
    }

    const int g = lane >> 2, t = lane & 3;
    int col0 = bn + wn * 32;
    int mat = col0 >> 10;
    int cm = col0 & 1023;
    int hh = cm >> 6;
    int d0 = cm & 63;
    __half* BQ = (mat == 0) ? g_q : (mat == 1) ? g_k : g_v;
    const float qs = (mat == 0) ? QSCALE : 1.0f;
#pragma unroll
    for (int mf = 0; mf < 2; mf++) {
        int rg = bm + wm * 32 + mf * 16 + g;
        int bb = rg >> 11, l = rg & 2047;
        size_t base = ((size_t)(bb * NHEADS + hh) * SEQ + l) * HDIM;
#pragma unroll
        for (int nf = 0; nf < 4; nf++) {
            int d = d0 + nf * 8 + t * 2;
            *(uint32_t*)(BQ + base + d) =
                pack2h(acc[mf][nf][0] * qs, acc[mf][nf][1] * qs);
            *(uint32_t*)(BQ + base + 8 * HDIM + d) =
                pack2h(acc[mf][nf][2] * qs, acc[mf][nf][3] * qs);
        }
    }
}

// ---------------------------------------------------------------------------
// Proj GEMM (proven R12/R13): CTA 128x128, 2 CTAs/SM, single wave.
// ---------------------------------------------------------------------------
#define PST 32768
#define PBOFF 16384
#define PSMEM (3 * PST)

__global__ __launch_bounds__(256, 2)
void gemm_proj(float* __restrict__ Cout)
{
    const int N = DIM;
    extern __shared__ char sm[];
    const uint32_t sb = smem_u32(sm);
    const int tid = threadIdx.x, lane = tid & 31, wid = tid >> 5;
    const int wm = wid >> 1, wn = wid & 1;
    const int bm = blockIdx.y * 128, bn = blockIdx.x * 128;

    const int ldrow = tid >> 1;
    const int ldc0 = (tid & 1) * 4;

    auto load_stage = [&](int ch, int s) {
        const __half* a = g_aoh + (size_t)(bm + ldrow) * DIM + ch * 64;
        const __half* b = g_wph + (size_t)(bn + ldrow) * DIM + ch * 64;
        uint32_t rbase = sb + s * PST + ldrow * 128;
#pragma unroll
        for (int i = 0; i < 4; i++) {
            int c16 = ldc0 + i;
            uint32_t sw = rbase + (uint32_t)((c16 ^ (ldrow & 7)) << 4);
            CPA16(sw, a + c16 * 8);
            CPA16(sw + PBOFF, b + c16 * 8);
        }
        CP_COMMIT();
    };

    load_stage(0, 0);
    load_stage(1, 1);

    float acc[2][8][4];
#pragma unroll
    for (int i = 0; i < 2; i++)
#pragma unroll
        for (int j = 0; j < 8; j++)
#pragma unroll
            for (int q = 0; q < 4; q++) acc[i][j][q] = 0.f;

    const int arow0 = wm * 32 + (lane & 15);
    const int alc = lane >> 4;
    const int brow0 = wn * 64 + ((lane >> 4) & 1) * 8 + (lane & 7);
    const int bc = (lane >> 3) & 1;

    for (int ch = 0; ch < NCHT; ch++) {
        const int s = ch % 3;
        if (ch + 1 < NCHT) { asm volatile("cp.async.wait_group 1;" ::: "memory"); }
        else               { asm volatile("cp.async.wait_group 0;" ::: "memory"); }
        __syncthreads();
        const uint32_t Ab = sb + s * PST;
        const uint32_t Bb = Ab + PBOFF;
#pragma unroll
        for (int kk = 0; kk < 4; kk++) {
            uint32_t a0[4], a1[4];
            {
                int c = kk * 2 + alc;
                int r0 = arow0;
                ldsm4(a0, Ab + r0 * 128 + ((c ^ (r0 & 7)) << 4));
                int r1 = arow0 + 16;
                ldsm4(a1, Ab + r1 * 128 + ((c ^ (r1 & 7)) << 4));
            }
#pragma unroll
            for (int bp = 0; bp < 4; bp++) {
                uint32_t b[4];
                int r = brow0 + bp * 16;
                int c = kk * 2 + bc;
                ldsm4(b, Bb + r * 128 + ((c ^ (r & 7)) << 4));
                mma_f16(acc[0][2 * bp],     a0, b);
                mma_f16(acc[0][2 * bp + 1], a0, b + 2);
                mma_f16(acc[1][2 * bp],     a1, b);
                mma_f16(acc[1][2 * bp + 1], a1, b + 2);
            }
        }
        if (ch + 2 < NCHT) load_stage(ch + 2, (ch + 2) % 3);
    }

    const int g = lane >> 2, t = lane & 3;
#pragma unroll
    for (int mf = 0; mf < 2; mf++) {
        int row = bm + wm * 32 + mf * 16 + g;
#pragma unroll
        for (int nf = 0; nf < 8; nf++) {
            int col = bn + wn * 64 + nf * 8 + t * 2;
            *(float2*)(Cout + (size_t)row * N + col) =
                make_float2(acc[mf][nf][0], acc[mf][nf][1]);
            *(float2*)(Cout + (size_t)(row + 8) * N + col) =
                make_float2(acc[mf][nf][2], acc[mf][nf][3]);
        }
    }
}

// ---------------------------------------------------------------------------
// Flash attention (R13 proven) with reordered prologue: Q cp.async issued
// first, then KV stages 0/1, then wait_group 2 (drains Q while KV flies).
// smem: 3 x 32KB KV stages + Q 16KB = 112KB.
// ---------------------------------------------------------------------------
#define AT_SMEM 114688
#define NIT2 (SEQ / 128)      // 16

__global__ __launch_bounds__(256, 2)
void attn_tc()
{
    extern __shared__ char smem[];
    const uint32_t sb = smem_u32(smem);
    const int tid = threadIdx.x, lane = tid & 31, wid = tid >> 5;
    const int b = blockIdx.z, h = blockIdx.y, q0 = blockIdx.x * 128;
    const size_t bh = (size_t)(b * NHEADS + h) * SEQ;

    const uint32_t QB = sb + 3 * 32768;

    auto load_kv = [&](int it, int s) {
        const size_t rb = bh + (size_t)it * 128;
        uint32_t dst = sb + s * 32768;
#pragma unroll
        for (int i = 0; i < 4; i++) {
            int idx = i * 256 + tid;          // 0..1023
            int row = idx >> 3, c16 = idx & 7;
            uint32_t sw = dst + row * 128 + ((c16 ^ (row & 7)) << 4);
            CPA16(sw, g_k + (rb + row) * HDIM + c16 * 8);
            CPA16(sw + 16384, g_v + (rb + row) * HDIM + c16 * 8);
        }
        CP_COMMIT();
    };

    // ---- prologue: Q first, then KV0, KV1; wait only for Q ----
    {
        const __half* src = g_q + (bh + q0) * HDIM;
#pragma unroll
        for (int i = 0; i < 4; i++) {
            int idx = i * 256 + tid;
            int row = idx >> 3, c16 = idx & 7;
            uint32_t sw = QB + row * 128 + ((c16 ^ (row & 7)) << 4);
            CPA16(sw, src + (size_t)row * HDIM + c16 * 8);
        }
        CP_COMMIT();
    }
    load_kv(0, 0);
    load_kv(1, 1);
    asm volatile("cp.async.wait_group 2;" ::: "memory");   // Q resident
    __syncthreads();

    uint32_t qf[4][4];
    {
        int r = wid * 16 + (lane & 15);
        int cl = lane >> 4;
#pragma unroll
        for (int kk = 0; kk < 4; kk++)
            ldsm4(qf[kk], QB + r * 128 + (((kk * 2 + cl) ^ (r & 7)) << 4));
    }

    float o[8][4];
#pragma unroll
    for (int i = 0; i < 8; i++)
#pragma unroll
        for (int j = 0; j < 4; j++) o[i][j] = 0.f;
    float m0 = -1e30f, m1 = -1e30f, l0s = 0.f, l1s = 0.f;

    const int brow0 = ((lane >> 4) & 1) * 8 + (lane & 7);
    const int bc = (lane >> 3) & 1;
    const int vlc = lane >> 4;

    for (int it = 0; it < NIT2; it++) {
        const int s = it % 3;
        if (it + 1 < NIT2) { asm volatile("cp.async.wait_group 1;" ::: "memory"); }
        else               { asm volatile("cp.async.wait_group 0;" ::: "memory"); }
        __syncthreads();
        if (it + 2 < NIT2) load_kv(it + 2, (it + 2) % 3);

#pragma unroll
        for (int sub = 0; sub < 2; sub++) {
            const uint32_t KB = sb + s * 32768 + sub * 8192;
            const uint32_t VB = sb + s * 32768 + 16384 + sub * 8192;

            // ---- S = Q K^T (exp2 domain via pre-scaled Q) ----
            float sx[8][4];
#pragma unroll
            for (int i = 0; i < 8; i++)
#pragma unroll
                for (int j = 0; j < 4; j++) sx[i][j] = 0.f;
#pragma unroll
            for (int kk = 0; kk < 4; kk++) {
#pragma unroll
                for (int bp = 0; bp < 4; bp++) {
                    uint32_t kfrag[4];
                    int r = brow0 + bp * 16;
                    int c = kk * 2 + bc;
                    ldsm4(kfrag, KB + r * 128 + ((c ^ (r & 7)) << 4));
                    mma_f16(sx[2 * bp],     qf[kk], kfrag);
                    mma_f16(sx[2 * bp + 1], qf[kk], kfrag + 2);
                }
            }

            // ---- online softmax ----
            float rmax0 = -1e30f, rmax1 = -1e30f;
#pragma unroll
            for (int nf = 0; nf < 8; nf++) {
                rmax0 = fmaxf(rmax0, fmaxf(sx[nf][0], sx[nf][1]));
                rmax1 = fmaxf(rmax1, fmaxf(sx[nf][2], sx[nf][3]));
            }
            rmax0 = fmaxf(rmax0, __shfl_xor_sync(0xffffffffu, rmax0, 1));
            rmax0 = fmaxf(rmax0, __shfl_xor_sync(0xffffffffu, rmax0, 2));
            rmax1 = fmaxf(rmax1, __shfl_xor_sync(0xffffffffu, rmax1, 1));
            rmax1 = fmaxf(rmax1, __shfl_xor_sync(0xffffffffu, rmax1, 2));
            float mn0 = fmaxf(m0, rmax0), mn1 = fmaxf(m1, rmax1);
            float corr0 = ex2(m0 - mn0), corr1 = ex2(m1 - mn1);
            float sum0 = 0.f, sum1 = 0.f;
#pragma unroll
            for (int nf = 0; nf < 8; nf++) {
                sx[nf][0] = ex2(sx[nf][0] - mn0);
                sx[nf][1] = ex2(sx[nf][1] - mn0);
                sx[nf][2] = ex2(sx[nf][2] - mn1);
                sx[nf][3] = ex2(sx[nf][3] - mn1);
                sum0 += sx[nf][0] + sx[nf][1];
                sum1 += sx[nf][2] + sx[nf][3];
            }
            sum0 += __shfl_xor_sync(0xffffffffu, sum0, 1);
            sum0 += __shfl_xor_sync(0xffffffffu, sum0, 2);
            sum1 += __shfl_xor_sync(0xffffffffu, sum1, 1);
            sum1 += __shfl_xor_sync(0xffffffffu, sum1, 2);
            l0s = l0s * corr0 + sum0;
            l1s = l1s * corr1 + sum1;
            m0 = mn0; m1 = mn1;
#pragma unroll
            for (int nf = 0; nf < 8; nf++) {
                o[nf][0] *= corr0; o[nf][1] *= corr0;
                o[nf][2] *= corr1; o[nf][3] *= corr1;
            }

            // ---- O += P V ----
#pragma unroll
            for (int kk = 0; kk < 4; kk++) {
                uint32_t pf[4];
                pf[0] = pack2h(sx[2 * kk][0], sx[2 * kk][1]);
                pf[1] = pack2h(sx[2 * kk][2], sx[2 * kk][3]);
                pf[2] = pack2h(sx[2 * kk + 1][0], sx[2 * kk + 1][1]);
                pf[3] = pack2h(sx[2 * kk + 1][2], sx[2 * kk + 1][3]);
#pragma unroll
                for (int hp = 0; hp < 4; hp++) {
                    uint32_t vf[4];
                    int r = kk * 16 + ((lane >> 3) & 1) * 8 + (lane & 7);
                    int c = hp * 2 + vlc;
                    ldsm4t(vf, VB + r * 128 + ((c ^ (r & 7)) << 4));
                    mma_f16(o[2 * hp],     pf, vf);
                    mma_f16(o[2 * hp + 1], pf, vf + 2);
                }
            }
        }
    }

    // ---- epilogue: fp16 proj operand ----
    const int g = lane >> 2, t = lane & 3;
    float inv0 = 1.f / l0s, inv1 = 1.f / l1s;
    size_t arow0 = (size_t)b * SEQ + q0 + wid * 16 + g;
#pragma unroll
    for (int nf = 0; nf < 8; nf++) {
        int col = h * 64 + nf * 8 + t * 2;
        *(uint32_t*)(g_aoh + arow0 * DIM + col) =
            pack2h(o[nf][0] * inv0, o[nf][1] * inv0);
        *(uint32_t*)(g_aoh + (arow0 + 8) * DIM + col) =
            pack2h(o[nf][2] * inv1, o[nf][3] * inv1);
    }
}

// ---------------------------------------------------------------------------
// Launch
// ---------------------------------------------------------------------------
extern "C" void kernel_launch(void* const* d_in, const int* in_sizes, int n_in,
                              void* d_out, int out_size)
{
    const float* x      = (const float*)d_in[0];
    const float* w_qkv  = (const float*)d_in[1];
    const float* w_proj = (const float*)d_in[2];
    float* out = (float*)d_out;
    (void)in_sizes; (void)n_in; (void)out_size;

    cudaFuncSetAttribute(gemm_qkv,  cudaFuncAttributeMaxDynamicSharedMemorySize, GSMEM);
    cudaFuncSetAttribute(gemm_proj, cudaFuncAttributeMaxDynamicSharedMemorySize, PSMEM);
    cudaFuncSetAttribute(attn_tc,   cudaFuncAttributeMaxDynamicSharedMemorySize, AT_SMEM);

    // merged fp32 -> fp16 conversion: 8M elements / 4096 per block
    split_all<<<2048, 256>>>(x, w_qkv, w_proj);

    // QKV projection (128x64, 3 CTAs/SM)
    gemm_qkv<<<dim3(3 * DIM / 64, MROWS / 128), 256, GSMEM>>>();

    // attention (128-row KV stages, 3-stage ring, overlapped prologue)
    attn_tc<<<dim3(SEQ / 128, NHEADS, BATCH), 256, AT_SMEM>>>();

    // output projection (128x128, 2 CTAs/SM, single wave)
    gemm_proj<<<dim3(DIM / 128, MROWS / 128), 256, PSMEM>>>(out);
}

// round 15
// speedup vs baseline: 1.0148x; 1.0148x over previous
#include <cuda_runtime.h>
#include <cuda_fp16.h>
#include <cstdint>

#define BATCH 2
#define SEQ 2048
#define DIM 1024
#define NHEADS 16
#define HDIM 64
#define QSCALE 0.1803368801111204f   // (1/8) * log2(e)
#define MROWS 4096

// ---------------------------------------------------------------------------
// Scratch (device globals: allocation-free)
// ---------------------------------------------------------------------------
__device__ __align__(16) __half g_xh [(size_t)MROWS * DIM];
__device__ __align__(16) __half g_wqh[(size_t)3 * DIM * DIM];
__device__ __align__(16) __half g_wph[(size_t)DIM * DIM];
__device__ __align__(16) __half g_aoh[(size_t)MROWS * DIM];

#define QKV_ELEMS ((size_t)BATCH * NHEADS * SEQ * HDIM)
__device__ __align__(16) __half g_q[QKV_ELEMS];   // pre-scaled by QSCALE
__device__ __align__(16) __half g_k[QKV_ELEMS];
__device__ __align__(16) __half g_v[QKV_ELEMS];

// ---------------------------------------------------------------------------
// Base-ISA helpers
// ---------------------------------------------------------------------------
__device__ __forceinline__ uint32_t smem_u32(const void* p) {
    uint32_t a;
    asm("{ .reg .u64 t; cvta.to.shared.u64 t, %1; cvt.u32.u64 %0, t; }"
        : "=r"(a) : "l"(p));
    return a;
}
__device__ __forceinline__ void ldsm4(uint32_t* r, uint32_t a) {
    asm volatile("ldmatrix.sync.aligned.m8n8.x4.shared.b16 {%0,%1,%2,%3}, [%4];"
        : "=r"(r[0]), "=r"(r[1]), "=r"(r[2]), "=r"(r[3]) : "r"(a));
}
__device__ __forceinline__ void ldsm4t(uint32_t* r, uint32_t a) {
    asm volatile("ldmatrix.sync.aligned.m8n8.x4.trans.shared.b16 {%0,%1,%2,%3}, [%4];"
        : "=r"(r[0]), "=r"(r[1]), "=r"(r[2]), "=r"(r[3]) : "r"(a));
}
__device__ __forceinline__ void mma_f16(float* c, const uint32_t* a, const uint32_t* b) {
    asm volatile(
        "mma.sync.aligned.m16n8k16.row.col.f32.f16.f16.f32 "
        "{%0,%1,%2,%3}, {%4,%5,%6,%7}, {%8,%9}, {%0,%1,%2,%3};"
        : "+f"(c[0]), "+f"(c[1]), "+f"(c[2]), "+f"(c[3])
        : "r"(a[0]), "r"(a[1]), "r"(a[2]), "r"(a[3]), "r"(b[0]), "r"(b[1]));
}
#define CPA16(d, s) \
    asm volatile("cp.async.cg.shared.global [%0], [%1], 16;" :: "r"(d), "l"(s))
#define CP_COMMIT() asm volatile("cp.async.commit_group;" ::: "memory")

__device__ __forceinline__ float ex2(float x) {
    float r; asm("ex2.approx.f32 %0, %1;" : "=f"(r) : "f"(x)); return r;
}
__device__ __forceinline__ uint32_t pack2h(float x, float y) {
    __half2 t = __floats2half2_rn(x, y);
    return *reinterpret_cast<uint32_t*>(&t);
}

// ---------------------------------------------------------------------------
// Merged split: one launch, 8 floats per thread (R13 proven).
// ---------------------------------------------------------------------------
#define XN  ((size_t)MROWS * DIM)        // 4M
#define WQN ((size_t)3 * DIM * DIM)      // 3M

__global__ void split_all(const float* __restrict__ x,
                          const float* __restrict__ wq,
                          const float* __restrict__ wp)
{
    size_t idx = (size_t)blockIdx.x * 2048 + (size_t)threadIdx.x * 8;
    const float* src;
    __half* dst;
    if (idx < XN)            { src = x  + idx;              dst = g_xh  + idx; }
    else if (idx < XN + WQN) { src = wq + (idx - XN);       dst = g_wqh + (idx - XN); }
    else                     { src = wp + (idx - XN - WQN); dst = g_wph + (idx - XN - WQN); }
    float4 a = *(const float4*)(src);
    float4 b = *(const float4*)(src + 4);
    *(uint2*)(dst)     = make_uint2(pack2h(a.x, a.y), pack2h(a.z, a.w));
    *(uint2*)(dst + 4) = make_uint2(pack2h(b.x, b.y), pack2h(b.z, b.w));
}

// ---------------------------------------------------------------------------
// QKV GEMM (proven): CTA 128x64, 3 CTAs/SM, fused fp16 Q/K/V epilogue.
// ---------------------------------------------------------------------------
#define GST 24576
#define GBOFF 16384
#define GSMEM (3 * GST)
#define NCHT 16

__global__ __launch_bounds__(256, 3)
void gemm_qkv()
{
    extern __shared__ char sm[];
    const uint32_t sb = smem_u32(sm);
    const int tid = threadIdx.x, lane = tid & 31, wid = tid >> 5;
    const int wm = wid >> 1, wn = wid & 1;
    const int bm = blockIdx.y * 128, bn = blockIdx.x * 64;

    const int lra = tid >> 1;
    const int lca = (tid & 1) * 4;
    const int lrb = tid >> 2;
    const int lcb = (tid & 3) * 2;

    auto load_stage = [&](int ch, int s) {
        const int co = ch * 64;
        uint32_t abase = sb + s * GST + lra * 128;
        const __half* a = g_xh + (size_t)(bm + lra) * DIM + co;
#pragma unroll
        for (int i = 0; i < 4; i++) {
            int c16 = lca + i;
            CPA16(abase + (uint32_t)((c16 ^ (lra & 7)) << 4), a + c16 * 8);
        }
        uint32_t bbase = sb + s * GST + GBOFF + lrb * 128;
        const __half* b = g_wqh + (size_t)(bn + lrb) * DIM + co;
#pragma unroll
        for (int i = 0; i < 2; i++) {
            int c16 = lcb + i;
            CPA16(bbase + (uint32_t)((c16 ^ (lrb & 7)) << 4), b + c16 * 8);
        }
        CP_COMMIT();
    };

    load_stage(0, 0);
    load_stage(1, 1);

    float acc[2][4][4];
#pragma unroll
    for (int i = 0; i < 2; i++)
#pragma unroll
        for (int j = 0; j < 4; j++)
#pragma unroll
            for (int q = 0; q < 4; q++) acc[i][j][q] = 0.f;

    const int arow0 = wm * 32 + (lane & 15);
    const int alc = lane >> 4;
    const int brow0 = wn * 32 + ((lane >> 4) & 1) * 8 + (lane & 7);
    const int bc = (lane >> 3) & 1;

    for (int ch = 0; ch < NCHT; ch++) {
        const int s = ch % 3;
        if (ch + 1 < NCHT) { asm volatile("cp.async.wait_group 1;" ::: "memory"); }
        else               { asm volatile("cp.async.wait_group 0;" ::: "memory"); }
        __syncthreads();
        const uint32_t Ab = sb + s * GST;
        const uint32_t Bb = Ab + GBOFF;
#pragma unroll
        for (int kk = 0; kk < 4; kk++) {
            uint32_t a0[4], a1[4];
            {
                int c = kk * 2 + alc;
                int r0 = arow0;
                ldsm4(a0, Ab + r0 * 128 + ((c ^ (r0 & 7)) << 4));
                int r1 = arow0 + 16;
                ldsm4(a1, Ab + r1 * 128 + ((c ^ (r1 & 7)) << 4));
            }
#pragma unroll
            for (int bp = 0; bp < 2; bp++) {
                uint32_t b[4];
                int r = brow0 + bp * 16;
                int c = kk * 2 + bc;
                ldsm4(b, Bb + r * 128 + ((c ^ (r & 7)) << 4));
                mma_f16(acc[0][2 * bp],     a0, b);
                mma_f16(acc[0][2 * bp + 1], a0, b + 2);
                mma_f16(acc[1][2 * bp],     a1, b);
                mma_f16(acc[1][2 * bp + 1], a1, b + 2);
            }
        }
        if (ch + 2 < NCHT) load_stage(ch + 2, (ch + 2) % 3);
    }

    const int g = lane >> 2, t = lane & 3;
    int col0 = bn + wn * 32;
    int mat = col0 >> 10;
    int cm = col0 & 1023;
    int hh = cm >> 6;
    int d0 = cm & 63;
    __half* BQ = (mat == 0) ? g_q : (mat == 1) ? g_k : g_v;
    const float qs = (mat == 0) ? QSCALE : 1.0f;
#pragma unroll
    for (int mf = 0; mf < 2; mf++) {
        int rg = bm + wm * 32 + mf * 16 + g;
        int bb = rg >> 11, l = rg & 2047;
        size_t base = ((size_t)(bb * NHEADS + hh) * SEQ + l) * HDIM;
#pragma unroll
        for (int nf = 0; nf < 4; nf++) {
            int d = d0 + nf * 8 + t * 2;
            *(uint32_t*)(BQ + base + d) =
                pack2h(acc[mf][nf][0] * qs, acc[mf][nf][1] * qs);
            *(uint32_t*)(BQ + base + 8 * HDIM + d) =
                pack2h(acc[mf][nf][2] * qs, acc[mf][nf][3] * qs);
        }
    }
}

// ---------------------------------------------------------------------------
// Proj GEMM (proven): CTA 128x128, 2 CTAs/SM, single wave.
// ---------------------------------------------------------------------------
#define PST 32768
#define PBOFF 16384
#define PSMEM (3 * PST)

__global__ __launch_bounds__(256, 2)
void gemm_proj(float* __restrict__ Cout)
{
    const int N = DIM;
    extern __shared__ char sm[];
    const uint32_t sb = smem_u32(sm);
    const int tid = threadIdx.x, lane = tid & 31, wid = tid >> 5;
    const int wm = wid >> 1, wn = wid & 1;
    const int bm = blockIdx.y * 128, bn = blockIdx.x * 128;

    const int ldrow = tid >> 1;
    const int ldc0 = (tid & 1) * 4;

    auto load_stage = [&](int ch, int s) {
        const __half* a = g_aoh + (size_t)(bm + ldrow) * DIM + ch * 64;
        const __half* b = g_wph + (size_t)(bn + ldrow) * DIM + ch * 64;
        uint32_t rbase = sb + s * PST + ldrow * 128;
#pragma unroll
        for (int i = 0; i < 4; i++) {
            int c16 = ldc0 + i;
            uint32_t sw = rbase + (uint32_t)((c16 ^ (ldrow & 7)) << 4);
            CPA16(sw, a + c16 * 8);
            CPA16(sw + PBOFF, b + c16 * 8);
        }
        CP_COMMIT();
    };

    load_stage(0, 0);
    load_stage(1, 1);

    float acc[2][8][4];
#pragma unroll
    for (int i = 0; i < 2; i++)
#pragma unroll
        for (int j = 0; j < 8; j++)
#pragma unroll
            for (int q = 0; q < 4; q++) acc[i][j][q] = 0.f;

    const int arow0 = wm * 32 + (lane & 15);
    const int alc = lane >> 4;
    const int brow0 = wn * 64 + ((lane >> 4) & 1) * 8 + (lane & 7);
    const int bc = (lane >> 3) & 1;

    for (int ch = 0; ch < NCHT; ch++) {
        const int s = ch % 3;
        if (ch + 1 < NCHT) { asm volatile("cp.async.wait_group 1;" ::: "memory"); }
        else               { asm volatile("cp.async.wait_group 0;" ::: "memory"); }
        __syncthreads();
        const uint32_t Ab = sb + s * PST;
        const uint32_t Bb = Ab + PBOFF;
#pragma unroll
        for (int kk = 0; kk < 4; kk++) {
            uint32_t a0[4], a1[4];
            {
                int c = kk * 2 + alc;
                int r0 = arow0;
                ldsm4(a0, Ab + r0 * 128 + ((c ^ (r0 & 7)) << 4));
                int r1 = arow0 + 16;
                ldsm4(a1, Ab + r1 * 128 + ((c ^ (r1 & 7)) << 4));
            }
#pragma unroll
            for (int bp = 0; bp < 4; bp++) {
                uint32_t b[4];
                int r = brow0 + bp * 16;
                int c = kk * 2 + bc;
                ldsm4(b, Bb + r * 128 + ((c ^ (r & 7)) << 4));
                mma_f16(acc[0][2 * bp],     a0, b);
                mma_f16(acc[0][2 * bp + 1], a0, b + 2);
                mma_f16(acc[1][2 * bp],     a1, b);
                mma_f16(acc[1][2 * bp + 1], a1, b + 2);
            }
        }
        if (ch + 2 < NCHT) load_stage(ch + 2, (ch + 2) % 3);
    }

    const int g = lane >> 2, t = lane & 3;
#pragma unroll
    for (int mf = 0; mf < 2; mf++) {
        int row = bm + wm * 32 + mf * 16 + g;
#pragma unroll
        for (int nf = 0; nf < 8; nf++) {
            int col = bn + wn * 64 + nf * 8 + t * 2;
            *(float2*)(Cout + (size_t)row * N + col) =
                make_float2(acc[mf][nf][0], acc[mf][nf][1]);
            *(float2*)(Cout + (size_t)(row + 8) * N + col) =
                make_float2(acc[mf][nf][2], acc[mf][nf][3]);
        }
    }
}

// ---------------------------------------------------------------------------
// Flash attention (R13 proven): 3-stage ring of 128-row KV tiles, serialized
// Q-wait prologue (staggers the cp.async burst across CTAs).
// smem: 3 x 32KB KV stages + Q 16KB = 112KB.
// ---------------------------------------------------------------------------
#define AT_SMEM 114688
#define NIT2 (SEQ / 128)      // 16

__global__ __launch_bounds__(256, 2)
void attn_tc()
{
    extern __shared__ char smem[];
    const uint32_t sb = smem_u32(smem);
    const int tid = threadIdx.x, lane = tid & 31, wid = tid >> 5;
    const int b = blockIdx.z, h = blockIdx.y, q0 = blockIdx.x * 128;
    const size_t bh = (size_t)(b * NHEADS + h) * SEQ;

    // ---- stage Q (128x64 fp16 = 16 KB) ----
    const uint32_t QB = sb + 3 * 32768;
    {
        const __half* src = g_q + (bh + q0) * HDIM;
#pragma unroll
        for (int i = 0; i < 4; i++) {
            int idx = i * 256 + tid;
            int row = idx >> 3, c16 = idx & 7;
            uint32_t sw = QB + row * 128 + ((c16 ^ (row & 7)) << 4);
            CPA16(sw, src + (size_t)row * HDIM + c16 * 8);
        }
        CP_COMMIT();
        asm volatile("cp.async.wait_group 0;" ::: "memory");
    }
    __syncthreads();

    uint32_t qf[4][4];
    {
        int r = wid * 16 + (lane & 15);
        int cl = lane >> 4;
#pragma unroll
        for (int kk = 0; kk < 4; kk++)
            ldsm4(qf[kk], QB + r * 128 + (((kk * 2 + cl) ^ (r & 7)) << 4));
    }

    // load one 128-row KV stage (K 16KB + V 16KB)
    auto load_kv = [&](int it, int s) {
        const size_t rb = bh + (size_t)it * 128;
        uint32_t dst = sb + s * 32768;
#pragma unroll
        for (int i = 0; i < 4; i++) {
            int idx = i * 256 + tid;          // 0..1023
            int row = idx >> 3, c16 = idx & 7;
            uint32_t sw = dst + row * 128 + ((c16 ^ (row & 7)) << 4);
            CPA16(sw, g_k + (rb + row) * HDIM + c16 * 8);
            CPA16(sw + 16384, g_v + (rb + row) * HDIM + c16 * 8);
        }
        CP_COMMIT();
    };

    load_kv(0, 0);
    load_kv(1, 1);

    float o[8][4];
#pragma unroll
    for (int i = 0; i < 8; i++)
#pragma unroll
        for (int j = 0; j < 4; j++) o[i][j] = 0.f;
    float m0 = -1e30f, m1 = -1e30f, l0s = 0.f, l1s = 0.f;

    const int brow0 = ((lane >> 4) & 1) * 8 + (lane & 7);
    const int bc = (lane >> 3) & 1;
    const int vlc = lane >> 4;

    for (int it = 0; it < NIT2; it++) {
        const int s = it % 3;
        if (it + 1 < NIT2) { asm volatile("cp.async.wait_group 1;" ::: "memory"); }
        else               { asm volatile("cp.async.wait_group 0;" ::: "memory"); }
        __syncthreads();
        if (it + 2 < NIT2) load_kv(it + 2, (it + 2) % 3);

#pragma unroll
        for (int sub = 0; sub < 2; sub++) {
            const uint32_t KB = sb + s * 32768 + sub * 8192;
            const uint32_t VB = sb + s * 32768 + 16384 + sub * 8192;

            // ---- S = Q K^T (exp2 domain via pre-scaled Q) ----
            float sx[8][4];
#pragma unroll
            for (int i = 0; i < 8; i++)
#pragma unroll
                for (int j = 0; j < 4; j++) sx[i][j] = 0.f;
#pragma unroll
            for (int kk = 0; kk < 4; kk++) {
#pragma unroll
                for (int bp = 0; bp < 4; bp++) {
                    uint32_t kfrag[4];
                    int r = brow0 + bp * 16;
                    int c = kk * 2 + bc;
                    ldsm4(kfrag, KB + r * 128 + ((c ^ (r & 7)) << 4));
                    mma_f16(sx[2 * bp],     qf[kk], kfrag);
                    mma_f16(sx[2 * bp + 1], qf[kk], kfrag + 2);
                }
            }

            // ---- online softmax ----
            float rmax0 = -1e30f, rmax1 = -1e30f;
#pragma unroll
            for (int nf = 0; nf < 8; nf++) {
                rmax0 = fmaxf(rmax0, fmaxf(sx[nf][0], sx[nf][1]));
                rmax1 = fmaxf(rmax1, fmaxf(sx[nf][2], sx[nf][3]));
            }
            rmax0 = fmaxf(rmax0, __shfl_xor_sync(0xffffffffu, rmax0, 1));
            rmax0 = fmaxf(rmax0, __shfl_xor_sync(0xffffffffu, rmax0, 2));
            rmax1 = fmaxf(rmax1, __shfl_xor_sync(0xffffffffu, rmax1, 1));
            rmax1 = fmaxf(rmax1, __shfl_xor_sync(0xffffffffu, rmax1, 2));
            float mn0 = fmaxf(m0, rmax0), mn1 = fmaxf(m1, rmax1);
            float corr0 = ex2(m0 - mn0), corr1 = ex2(m1 - mn1);
            float sum0 = 0.f, sum1 = 0.f;
#pragma unroll
            for (int nf = 0; nf < 8; nf++) {
                sx[nf][0] = ex2(sx[nf][0] - mn0);
                sx[nf][1] = ex2(sx[nf][1] - mn0);
                sx[nf][2] = ex2(sx[nf][2] - mn1);
                sx[nf][3] = ex2(sx[nf][3] - mn1);
                sum0 += sx[nf][0] + sx[nf][1];
                sum1 += sx[nf][2] + sx[nf][3];
            }
            sum0 += __shfl_xor_sync(0xffffffffu, sum0, 1);
            sum0 += __shfl_xor_sync(0xffffffffu, sum0, 2);
            sum1 += __shfl_xor_sync(0xffffffffu, sum1, 1);
            sum1 += __shfl_xor_sync(0xffffffffu, sum1, 2);
            l0s = l0s * corr0 + sum0;
            l1s = l1s * corr1 + sum1;
            m0 = mn0; m1 = mn1;
#pragma unroll
            for (int nf = 0; nf < 8; nf++) {
                o[nf][0] *= corr0; o[nf][1] *= corr0;
                o[nf][2] *= corr1; o[nf][3] *= corr1;
            }

            // ---- O += P V ----
#pragma unroll
            for (int kk = 0; kk < 4; kk++) {
                uint32_t pf[4];
                pf[0] = pack2h(sx[2 * kk][0], sx[2 * kk][1]);
                pf[1] = pack2h(sx[2 * kk][2], sx[2 * kk][3]);
                pf[2] = pack2h(sx[2 * kk + 1][0], sx[2 * kk + 1][1]);
                pf[3] = pack2h(sx[2 * kk + 1][2], sx[2 * kk + 1][3]);
#pragma unroll
                for (int hp = 0; hp < 4; hp++) {
                    uint32_t vf[4];
                    int r = kk * 16 + ((lane >> 3) & 1) * 8 + (lane & 7);
                    int c = hp * 2 + vlc;
                    ldsm4t(vf, VB + r * 128 + ((c ^ (r & 7)) << 4));
                    mma_f16(o[2 * hp],     pf, vf);
                    mma_f16(o[2 * hp + 1], pf, vf + 2);
                }
            }
        }
    }

    // ---- epilogue: fp16 proj operand ----
    const int g = lane >> 2, t = lane & 3;
    float inv0 = 1.f / l0s, inv1 = 1.f / l1s;
    size_t arow0 = (size_t)b * SEQ + q0 + wid * 16 + g;
#pragma unroll
    for (int nf = 0; nf < 8; nf++) {
        int col = h * 64 + nf * 8 + t * 2;
        *(uint32_t*)(g_aoh + arow0 * DIM + col) =
            pack2h(o[nf][0] * inv0, o[nf][1] * inv0);
        *(uint32_t*)(g_aoh + (arow0 + 8) * DIM + col) =
            pack2h(o[nf][2] * inv1, o[nf][3] * inv1);
    }
}

// ---------------------------------------------------------------------------
// Launch
// ---------------------------------------------------------------------------
extern "C" void kernel_launch(void* const* d_in, const int* in_sizes, int n_in,
                              void* d_out, int out_size)
{
    const float* x      = (const float*)d_in[0];
    const float* w_qkv  = (const float*)d_in[1];
    const float* w_proj = (const float*)d_in[2];
    float* out = (float*)d_out;
    (void)in_sizes; (void)n_in; (void)out_size;

    cudaFuncSetAttribute(gemm_qkv,  cudaFuncAttributeMaxDynamicSharedMemorySize, GSMEM);
    cudaFuncSetAttribute(gemm_proj, cudaFuncAttributeMaxDynamicSharedMemorySize, PSMEM);
    cudaFuncSetAttribute(attn_tc,   cudaFuncAttributeMaxDynamicSharedMemorySize, AT_SMEM);

    // merged fp32 -> fp16 conversion: 8M elements / 2048 per block
    split_all<<<4096, 256>>>(x, w_qkv, w_proj);

    // QKV projection (128x64, 3 CTAs/SM)
    gemm_qkv<<<dim3(3 * DIM / 64, MROWS / 128), 256, GSMEM>>>();

    // attention (128-row KV stages, 3-stage ring)
    attn_tc<<<dim3(SEQ / 128, NHEADS, BATCH), 256, AT_SMEM>>>();

    // output projection (128x128, 2 CTAs/SM, single wave)
    gemm_proj<<<dim3(DIM / 128, MROWS / 128), 256, PSMEM>>>(out);
}